// round 3
// baseline (speedup 1.0000x reference)
#include <cuda_runtime.h>
#include <math.h>

// Problem constants (fixed by the dataset)
#define NE 4096
#define NW 8192
#define KD 128
#define GG 1024
#define MM 64
#define JJ 256

#define NBLK 592    // 148 SMs * 4 blocks — co-resident by construction
#define NTHR 256
#define NTILES 1024 // (8192/32) * (128/32) transpose tiles

// Scratch (device globals — no runtime allocation allowed)
__device__ float g_Wt[NW * KD];   // transposed W (4 MB, L2-resident)
__device__ float g_pr[NBLK];
__device__ float g_pw[NBLK];
__device__ float g_pe[NBLK];
__device__ float g_sim[GG];
__device__ float g_ent[2];
__device__ int   g_bar1 = 0;      // transpose-done counter
__device__ int   g_done = 0;      // completion ticket

__device__ __forceinline__ float block_reduce(float v) {
    __shared__ float sh[32];
    int lane = threadIdx.x & 31;
    int wid  = threadIdx.x >> 5;
    #pragma unroll
    for (int o = 16; o > 0; o >>= 1) v += __shfl_down_sync(0xffffffffu, v, o);
    __syncthreads();
    if (lane == 0) sh[wid] = v;
    __syncthreads();
    v = (threadIdx.x < (NTHR >> 5)) ? sh[threadIdx.x] : 0.0f;
    if (wid == 0) {
        #pragma unroll
        for (int o = 16; o > 0; o >>= 1) v += __shfl_down_sync(0xffffffffu, v, o);
    }
    return v;   // valid in thread 0
}

__global__ void __launch_bounds__(NTHR, 4)
fused_k(const float* __restrict__ actual,
        const float* __restrict__ pred,
        const float* __restrict__ W,
        const float* __restrict__ E,
        const float* __restrict__ Sw,
        const float* __restrict__ Se,
        const float* __restrict__ lamb,
        const int*   __restrict__ rowi,
        const int*   __restrict__ wi,
        const int*   __restrict__ ej,
        const int*   __restrict__ sj,
        float* __restrict__ out) {
    const int b = blockIdx.x;
    const int t = threadIdx.x;
    const int tid    = b * NTHR + t;
    const int stride = NBLK * NTHR;

    __shared__ float tile[32][33];
    __shared__ int   sh_idx[MM < JJ ? JJ : MM];

    // ---- Phase 0: transpose W (KD x NW) -> g_Wt (NW x KD), tiled ----
    {
        const int tx = t & 31, ty = t >> 5;           // 32 x 8 layout
        for (int tt = b; tt < NTILES; tt += NBLK) {
            const int tn = (tt & 255) * 32;           // n base
            const int tk = (tt >> 8) * 32;            // k base
            #pragma unroll
            for (int i = 0; i < 32; i += 8)
                tile[ty + i][tx] = W[(size_t)(tk + ty + i) * NW + (tn + tx)];
            __syncthreads();
            #pragma unroll
            for (int i = 0; i < 32; i += 8)
                g_Wt[(size_t)(tn + ty + i) * KD + (tk + tx)] = tile[tx][ty + i];
            __syncthreads();
        }
        __threadfence();
        if (t == 0) atomicAdd(&g_bar1, 1);
    }

    // ---- Entity term (block 0 only; independent of transpose) ----
    if (b == 0) {
        const int row = rowi[0];
        if (t < JJ) sh_idx[t] = ej[t];
        __syncthreads();
        float s_de = 0.0f;
        for (int i = t; i < JJ * KD; i += NTHR) {
            int jj = i >> 7;
            int kk = i & (KD - 1);
            float d = E[(size_t)row * KD + kk] - E[(size_t)sh_idx[jj] * KD + kk];
            s_de += d * d;
        }
        float s_se = (t < JJ) ? Se[(size_t)row * NE + sh_idx[t]] : 0.0f;
        float de = block_reduce(s_de);
        __syncthreads();
        float se = block_reduce(s_se);
        if (t == 0) { g_ent[0] = de; g_ent[1] = se; }
        __syncthreads();
    }

    const float4* a4 = (const float4*)actual;
    const float4* p4 = (const float4*)pred;
    const int n4  = (NE * NW) / 4;   // 8M
    const int n4h = n4 / 2;

    float s0 = 0.f, s1 = 0.f, s2 = 0.f, s3 = 0.f;

    // ---- Phase 1: first half of a-p (overlaps transpose stragglers) ----
    {
        int i = tid;
        for (; i + 3 * stride < n4h; i += 4 * stride) {
            float4 av0 = a4[i];
            float4 av1 = a4[i +     stride];
            float4 av2 = a4[i + 2 * stride];
            float4 av3 = a4[i + 3 * stride];
            float4 pv0 = p4[i];
            float4 pv1 = p4[i +     stride];
            float4 pv2 = p4[i + 2 * stride];
            float4 pv3 = p4[i + 3 * stride];
            float d;
            d = av0.x - pv0.x; s0 += d * d; d = av0.y - pv0.y; s0 += d * d;
            d = av0.z - pv0.z; s0 += d * d; d = av0.w - pv0.w; s0 += d * d;
            d = av1.x - pv1.x; s1 += d * d; d = av1.y - pv1.y; s1 += d * d;
            d = av1.z - pv1.z; s1 += d * d; d = av1.w - pv1.w; s1 += d * d;
            d = av2.x - pv2.x; s2 += d * d; d = av2.y - pv2.y; s2 += d * d;
            d = av2.z - pv2.z; s2 += d * d; d = av2.w - pv2.w; s2 += d * d;
            d = av3.x - pv3.x; s3 += d * d; d = av3.y - pv3.y; s3 += d * d;
            d = av3.z - pv3.z; s3 += d * d; d = av3.w - pv3.w; s3 += d * d;
        }
        for (; i < n4h; i += stride) {
            float4 av = a4[i];
            float4 pv = p4[i];
            float d;
            d = av.x - pv.x; s0 += d * d; d = av.y - pv.y; s0 += d * d;
            d = av.z - pv.z; s0 += d * d; d = av.w - pv.w; s0 += d * d;
        }
    }

    // ---- Barrier: wait for transpose completion (should be free by now) ----
    if (t == 0) {
        while (*(volatile int*)&g_bar1 != NBLK) { }
    }
    __syncthreads();
    __threadfence();   // acquire: make g_Wt writes visible

    // ---- Phase 2: word-gather groups (L2-resident Wt) ----
    for (int g = b; g < GG; g += NBLK) {
        const int j = sj[g];
        if (t < MM) sh_idx[t] = wi[g * MM + t];
        __syncthreads();

        const int k    = t & (KD - 1);
        const int half = t >> 7;            // 0 or 1: split m-range
        const float wjk = g_Wt[(size_t)j * KD + k];

        float acc = 0.0f;
        const int m0 = half * (MM / 2);
        #pragma unroll 8
        for (int m = m0; m < m0 + MM / 2; m++) {
            float d = wjk - g_Wt[(size_t)sh_idx[m] * KD + k];
            acc += d * d;
        }

        float swv = (t < MM) ? Sw[(size_t)j * NW + sh_idx[t]] : 0.0f;

        float d2 = block_reduce(acc);
        __syncthreads();
        float sw = block_reduce(swv);
        if (t == 0) g_sim[g] = sqrtf(d2) * sw;
        __syncthreads();
    }

    // ---- Phase 3: second half of a-p + relu norms ----
    {
        int i = n4h + tid;
        for (; i + 3 * stride < n4; i += 4 * stride) {
            float4 av0 = a4[i];
            float4 av1 = a4[i +     stride];
            float4 av2 = a4[i + 2 * stride];
            float4 av3 = a4[i + 3 * stride];
            float4 pv0 = p4[i];
            float4 pv1 = p4[i +     stride];
            float4 pv2 = p4[i + 2 * stride];
            float4 pv3 = p4[i + 3 * stride];
            float d;
            d = av0.x - pv0.x; s0 += d * d; d = av0.y - pv0.y; s0 += d * d;
            d = av0.z - pv0.z; s0 += d * d; d = av0.w - pv0.w; s0 += d * d;
            d = av1.x - pv1.x; s1 += d * d; d = av1.y - pv1.y; s1 += d * d;
            d = av1.z - pv1.z; s1 += d * d; d = av1.w - pv1.w; s1 += d * d;
            d = av2.x - pv2.x; s2 += d * d; d = av2.y - pv2.y; s2 += d * d;
            d = av2.z - pv2.z; s2 += d * d; d = av2.w - pv2.w; s2 += d * d;
            d = av3.x - pv3.x; s3 += d * d; d = av3.y - pv3.y; s3 += d * d;
            d = av3.z - pv3.z; s3 += d * d; d = av3.w - pv3.w; s3 += d * d;
        }
        for (; i < n4; i += stride) {
            float4 av = a4[i];
            float4 pv = p4[i];
            float d;
            d = av.x - pv.x; s0 += d * d; d = av.y - pv.y; s0 += d * d;
            d = av.z - pv.z; s0 += d * d; d = av.w - pv.w; s0 += d * d;
        }
    }
    float s_r = (s0 + s1) + (s2 + s3);

    float s_w = 0.0f;
    {
        const float4* w4 = (const float4*)W;
        const int nw4 = (KD * NW) / 4;
        for (int q = tid; q < nw4; q += stride) {
            float4 v = w4[q];
            float r0 = fmaxf(v.x, 0.f), r1 = fmaxf(v.y, 0.f);
            float r2 = fmaxf(v.z, 0.f), r3 = fmaxf(v.w, 0.f);
            s_w += r0 * r0 + r1 * r1 + r2 * r2 + r3 * r3;
        }
    }

    float s_e = 0.0f;
    {
        const float4* e4 = (const float4*)E;
        const int ne4 = (NE * KD) / 4;
        for (int q = tid; q < ne4; q += stride) {
            float4 v = e4[q];
            float r0 = fmaxf(v.x, 0.f), r1 = fmaxf(v.y, 0.f);
            float r2 = fmaxf(v.z, 0.f), r3 = fmaxf(v.w, 0.f);
            s_e += r0 * r0 + r1 * r1 + r2 * r2 + r3 * r3;
        }
    }

    // ---- Store per-block partials ----
    float br = block_reduce(s_r);
    __syncthreads();
    float bw = block_reduce(s_w);
    __syncthreads();
    float be = block_reduce(s_e);
    if (t == 0) {
        g_pr[b] = br;
        g_pw[b] = bw;
        g_pe[b] = be;
    }

    // ---- Completion ticket: last block composes the scalar ----
    __shared__ int amLast;
    __threadfence();
    if (t == 0) {
        int r = atomicAdd(&g_done, 1);
        amLast = (r == NBLK - 1);
    }
    __syncthreads();

    if (amLast) {
        __threadfence();   // acquire all partials
        float sr = 0.f, sw = 0.f, se = 0.f, sim = 0.f;
        for (int i = t; i < NBLK; i += NTHR) {
            sr += g_pr[i];
            sw += g_pw[i];
            se += g_pe[i];
        }
        for (int i = t; i < GG; i += NTHR) sim += g_sim[i];

        float Sr  = block_reduce(sr);   __syncthreads();
        float Sw_ = block_reduce(sw);   __syncthreads();
        float Se_ = block_reduce(se);   __syncthreads();
        float Sim = block_reduce(sim);

        if (t == 0) {
            float recon = sqrtf(Sr);
            float param = sqrtf(Sw_) + sqrtf(Se_);
            float sim_p = Sim + sqrtf(g_ent[0]) * g_ent[1];
            out[0] = recon + lamb[0] * param + sim_p;
            g_done = 0;    // reset for next graph replay
            g_bar1 = 0;
        }
    }
}

// ---------------------------------------------------------------------------
// Launch: one persistent fused kernel.
// Inputs (metadata order):
//  0 actual  1 prediction  2 W  3 E  4 Sw  5 Se  6 lamb  7 row_ind
//  8 word_i_indices  9 entity_j_indices  10 sample_j_indices
// ---------------------------------------------------------------------------
extern "C" void kernel_launch(void* const* d_in, const int* in_sizes, int n_in,
                              void* d_out, int out_size) {
    fused_k<<<NBLK, NTHR>>>(
        (const float*)d_in[0], (const float*)d_in[1],
        (const float*)d_in[2], (const float*)d_in[3],
        (const float*)d_in[4], (const float*)d_in[5],
        (const float*)d_in[6], (const int*)d_in[7],
        (const int*)d_in[8],   (const int*)d_in[9],
        (const int*)d_in[10],  (float*)d_out);
}